// round 10
// baseline (speedup 1.0000x reference)
#include <cuda_runtime.h>
#include <stdint.h>

// Shapes (fixed):
//   lstm : [4, 256, 128] f32   (512 KiB -> L1/L2 resident)
//   slic : [4, 512, 512] i32   (4 MiB, read once)
//   out  : [4, 512, 512, 128] f32 (512 MiB written -> the binding stream)
//
// R9: 256-bit vector memory ops (sm_100+ PTX: ld.global.nc.v8.f32 /
// st.global.cs.v8.f32). Same bytes, half the store instructions / LSU slots.
// Warp owns 4 pixels (2 KB): v8-store j covers pixels {2j,2j+1}; lanes 0-15
// handle the even pixel, lanes 16-31 the odd one, 32 B per lane.

namespace {
constexpr int S = 256;
constexpr int C = 128;                 // floats per pixel row
constexpr int HW_SHIFT = 18;           // 512*512 = 1<<18
constexpr long long NPIX = 4LL << HW_SHIFT;   // 1,048,576
constexpr int PIX_PER_WARP = 4;
constexpr int WARPS_PER_BLOCK = 16;    // 512 threads
constexpr int THREADS = WARPS_PER_BLOCK * 32;
constexpr int PIX_PER_BLOCK = WARPS_PER_BLOCK * PIX_PER_WARP;   // 64
}

__device__ __forceinline__ void ldg_nc_v8(const float* p, float* v) {
    asm volatile(
        "ld.global.nc.v8.f32 {%0,%1,%2,%3,%4,%5,%6,%7}, [%8];"
        : "=f"(v[0]), "=f"(v[1]), "=f"(v[2]), "=f"(v[3]),
          "=f"(v[4]), "=f"(v[5]), "=f"(v[6]), "=f"(v[7])
        : "l"(p));
}

__device__ __forceinline__ void stg_cs_v8(float* p, const float* v) {
    asm volatile(
        "st.global.cs.v8.f32 [%0], {%1,%2,%3,%4,%5,%6,%7,%8};"
        :: "l"(p),
           "f"(v[0]), "f"(v[1]), "f"(v[2]), "f"(v[3]),
           "f"(v[4]), "f"(v[5]), "f"(v[6]), "f"(v[7])
        : "memory");
}

__global__ __launch_bounds__(THREADS)
void convert2image_gather_v8(const float* __restrict__ lstm,
                             const int*   __restrict__ slic,
                             float*       __restrict__ out)
{
    const int lane = threadIdx.x & 31;
    const int warp = threadIdx.x >> 5;

    // First pixel of this warp's group of 4 (consecutive, 16B-aligned ids).
    const long long p0 = ((long long)blockIdx.x * WARPS_PER_BLOCK + warp)
                         * PIX_PER_WARP;

    // Group shares one batch (p0 % 4 == 0, HW % 4 == 0).
    const int b = (int)(p0 >> HW_SHIFT);
    const float* __restrict__ lstm_b = lstm + (long long)b * S * C;

    // 1) One warp-uniform int4 load covers all 4 segment ids.
    const int4 s = __ldg(reinterpret_cast<const int4*>(slic + p0));
    const int seg[PIX_PER_WARP] = { s.x - 1, s.y - 1, s.z - 1, s.w - 1 };

    const int half = lane >> 4;        // 0: even pixel, 1: odd pixel
    const int sub  = lane & 15;        // 32B chunk within the 512B row

    // 2) Two independent v8 gather loads (each half-warp reads its row).
    float v[2][8];
#pragma unroll
    for (int j = 0; j < 2; ++j) {
        const int sg = half ? seg[2 * j + 1] : seg[2 * j];
        ldg_nc_v8(lstm_b + (long long)sg * C + sub * 8, v[j]);
    }

    // 3) Two streaming v8 stores: 1 KB per instruction, 2 KB contiguous/warp.
    float* __restrict__ dst = out + p0 * (long long)C;
#pragma unroll
    for (int j = 0; j < 2; ++j)
        stg_cs_v8(dst + j * 256 + lane * 8, v[j]);
}

extern "C" void kernel_launch(void* const* d_in, const int* in_sizes, int n_in,
                              void* d_out, int out_size)
{
    const float* lstm = (const float*)d_in[0];
    const int*   slic = (const int*)d_in[1];
    float*       out  = (float*)d_out;

    (void)in_sizes; (void)n_in; (void)out_size;

    const int grid = (int)(NPIX / PIX_PER_BLOCK);   // 16384, exact
    convert2image_gather_v8<<<grid, THREADS>>>(lstm, slic, out);
}